// round 9
// baseline (speedup 1.0000x reference)
#include <cuda_runtime.h>
#include <cstdint>

#define Npts   20000
#define Msamp  5000
#define KNN    16
#define CIN    64
#define COUT   128
#define FDIM   (3 + CIN)          // 67
#define BN_EPS 1e-5f

// FPS cluster config (R6-verified core)
#define FPS_CTAS    8
#define FT          256
#define FPS_WARPS   8
#define FPS_SLOTS   (FPS_CTAS * FPS_WARPS)    // 64
#define FPS_PPC     (Npts / FPS_CTAS)         // 2500
#define FPS_PPT     10
#define SLOT_BYTES  24
// fused-grid knn consumers: 17 clusters total -> always resident in one wave
#define KNN_BLOCKS    128
#define GRID_FUSED    (FPS_CTAS + KNN_BLOCKS) // 136
#define KNN_WARPS_TOT (KNN_BLOCKS * 8)        // 1024
#define DYN_SMEM      (120 * 1024)            // forces 1 block/SM

// ---------------- device scratch (no allocs allowed) ----------------
__device__ float4   g_p4[Npts];
__device__ float4   g_q4[Msamp];
__device__ unsigned g_progress;               // #valid q4 entries (monotone per run)
__device__ int      g_nidx[Msamp * KNN];
__device__ float    g_maxh[Msamp * COUT];
__device__ float    g_minh[Msamp * COUT];
__device__ float    g_ps [Msamp * COUT];
__device__ float    g_pss[Msamp * COUT];
__device__ float    g_mean[COUT];
__device__ float    g_rstd[COUT];
__device__ float    g_np_scratch[Msamp * 3];

// ---------------- PTX helpers ----------------
__device__ __forceinline__ uint32_t smem_u32(const void* p) {
    uint32_t a;
    asm("{ .reg .u64 t; cvta.to.shared.u64 t, %1; cvt.u32.u64 %0, t; }" : "=r"(a) : "l"(p));
    return a;
}
__device__ __forceinline__ uint32_t mapa_u32(uint32_t local_addr, uint32_t rank) {
    uint32_t r;
    asm("mapa.shared::cluster.u32 %0, %1, %2;" : "=r"(r) : "r"(local_addr), "r"(rank));
    return r;
}
__device__ __forceinline__ void st_async_u64(uint32_t raddr, unsigned long long v,
                                             uint32_t rmbar) {
    asm volatile("st.async.shared::cluster.mbarrier::complete_tx::bytes.b64 [%0], %1, [%2];"
                 :: "r"(raddr), "l"(v), "r"(rmbar) : "memory");
}
__device__ __forceinline__ void mbar_init(uint32_t mbar, uint32_t cnt) {
    asm volatile("mbarrier.init.shared.b64 [%0], %1;" :: "r"(mbar), "r"(cnt) : "memory");
}
__device__ __forceinline__ void mbar_expect_tx(uint32_t mbar, uint32_t bytes) {
    asm volatile("mbarrier.arrive.expect_tx.shared.b64 _, [%0], %1;"
                 :: "r"(mbar), "r"(bytes) : "memory");
}
__device__ __forceinline__ void mbar_wait_parity(uint32_t mbar, uint32_t ph) {
    uint32_t done = 0;
    while (!done) {
        asm volatile(
            "{\n\t.reg .pred p;\n\t"
            "mbarrier.try_wait.parity.acquire.cluster.shared::cta.b64 p, [%1], %2, 0x989680;\n\t"
            "selp.b32 %0, 1, 0, p;\n\t}"
            : "=r"(done) : "r"(mbar), "r"(ph) : "memory");
    }
}
__device__ __forceinline__ unsigned long long pack2f(float a, float b) {
    return ((unsigned long long)__float_as_uint(b) << 32) | __float_as_uint(a);
}
__device__ __forceinline__ void st_release_u32(unsigned* p, unsigned v) {
    asm volatile("st.global.release.gpu.u32 [%0], %1;" :: "l"(p), "r"(v) : "memory");
}
__device__ __forceinline__ unsigned ld_acq_u32(const unsigned* p) {
    unsigned v;
    asm volatile("ld.global.acquire.gpu.u32 %0, [%1];" : "=r"(v) : "l"(p) : "memory");
    return v;
}
__device__ __forceinline__ float4 ld_acq_f4(const float4* p) {
    float4 v;
    asm volatile("ld.global.acquire.gpu.v4.f32 {%0,%1,%2,%3}, [%4];"
                 : "=f"(v.x), "=f"(v.y), "=f"(v.z), "=f"(v.w) : "l"(p) : "memory");
    return v;
}

// slot argmax: winning slot index + key (all lanes), tie -> lowest global idx
__device__ __forceinline__ int slot_reduce(const unsigned long long* slots, int lane,
                                           unsigned long long& wkey) {
    unsigned long long v0 = slots[lane * 3];
    unsigned long long v1 = slots[(lane + 32) * 3];
    unsigned d0 = (unsigned)(v0 >> 15), d1 = (unsigned)(v1 >> 15);
    unsigned dg = __reduce_max_sync(0xFFFFFFFFu, d0 > d1 ? d0 : d1);
    unsigned l = 0;
    if (d0 == dg) l = (unsigned)v0 & 0x7FFFu;
    if (d1 == dg) { unsigned l1 = (unsigned)v1 & 0x7FFFu; if (l1 > l) l = l1; }
    unsigned lg = __reduce_max_sync(0xFFFFFFFFu, l);
    wkey = ((unsigned long long)dg << 15) | lg;
    unsigned b0 = __ballot_sync(0xFFFFFFFFu, v0 == wkey);
    int sl;
    if (b0) sl = __ffs(b0) - 1;
    else {
        unsigned b1 = __ballot_sync(0xFFFFFFFFu, v1 == wkey);
        sl = 32 + __ffs(b1) - 1;
    }
    return sl;
}

// ---------------- pack ----------------
__global__ void pack_kernel(const float* __restrict__ p) {
    int i = blockIdx.x * blockDim.x + threadIdx.x;
    if (i < Npts) {
        float x = p[3 * i], y = p[3 * i + 1], z = p[3 * i + 2];
        float pp = __fadd_rn(__fadd_rn(__fmul_rn(x, x), __fmul_rn(y, y)), __fmul_rn(z, z));
        g_p4[i] = make_float4(x, y, z, pp);
    }
}

// ---------------- kNN warp scan (verified bit-exact) ----------------
#define INFKEY 0xFFFFFFFFFFFFFFFFull

__device__ __forceinline__ void knn_merge(unsigned long long* cand, int lane,
                                          unsigned long long& cur,
                                          unsigned long long& thr, int& cnt) {
    if (lane < 16) cand[64 + lane] = cur;
#pragma unroll
    for (int s = lane; s < 64; s += 32) if (s >= cnt) cand[s] = INFKEY;
    __syncwarp();
    unsigned long long picked = INFKEY, last = INFKEY;
#pragma unroll 1
    for (int r = 0; r < 16; r++) {
        unsigned long long a = cand[lane];
        unsigned long long b = cand[lane + 32];
        unsigned long long c = (lane < 16) ? cand[64 + lane] : INFKEY;
        unsigned long long v = a < b ? a : b;
        v = v < c ? v : c;
#pragma unroll
        for (int off = 16; off; off >>= 1) {
            unsigned long long o = __shfl_down_sync(0xFFFFFFFFu, v, off);
            if (o < v) v = o;
        }
        v = __shfl_sync(0xFFFFFFFFu, v, 0);
        if (a == v)                       cand[lane]      = INFKEY;
        else if (b == v)                  cand[lane + 32] = INFKEY;
        else if (lane < 16 && c == v)     cand[64 + lane] = INFKEY;
        __syncwarp();
        if (lane == r) picked = v;
        last = v;
    }
    cur = picked; thr = last; cnt = 0;
    __syncwarp();
}

__device__ __forceinline__ void knn_query(const float4 Q, int q, int lane,
                                          unsigned long long* cand) {
    unsigned long long cur = INFKEY, thr = INFKEY;
    int cnt = 0;
#pragma unroll 1
    for (int s = 0; s < Npts / 32; s++) {
        int idx = lane + 32 * s;
        float4 P = __ldg(&g_p4[idx]);
        float dot = __fmaf_rn(Q.z, P.z, __fmaf_rn(Q.y, P.y, __fmul_rn(Q.x, P.x)));
        float d = __fadd_rn(__fsub_rn(Q.w, __fmul_rn(2.0f, dot)), P.w);
        unsigned ub = __float_as_uint(d);
        ub ^= (ub >> 31) ? 0xFFFFFFFFu : 0x80000000u;
        unsigned long long k = ((unsigned long long)ub << 32) | (unsigned)idx;
        bool pred = k < thr;
        unsigned bal = __ballot_sync(0xFFFFFFFFu, pred);
        if (pred) {
            int pos = cnt + __popc(bal & ((1u << lane) - 1u));
            cand[pos] = k;
        }
        cnt += __popc(bal);
        if (cnt >= 32) knn_merge(cand, lane, cur, thr, cnt);
    }
    if (cnt > 0) knn_merge(cand, lane, cur, thr, cnt);
    if (lane < 16) g_nidx[q * KNN + lane] = (int)(unsigned)(cur & 0xFFFFFFFFull);
}

// ---------------- fused: FPS (cluster of blocks 0-7) + polling kNN ----------------
__global__ void __cluster_dims__(FPS_CTAS, 1, 1) __launch_bounds__(FT, 1)
fused_kernel(float* __restrict__ out_np) {
    extern __shared__ unsigned long long dyn_smem[];
    __shared__ unsigned long long s_slots[2][FPS_SLOTS * 3];
    __shared__ unsigned long long s_mbar[2];
    const int t = threadIdx.x, warp = t >> 5, lane = t & 31;

    if (blockIdx.x < FPS_CTAS) {
        // ======================= FPS (R6 core) =======================
        uint32_t cta;
        asm("mov.u32 %0, %%cluster_ctarank;" : "=r"(cta));
        const uint32_t slot_base = smem_u32(&s_slots[0][0]);
        const uint32_t mbar_base = smem_u32(&s_mbar[0]);
        if (t == 0) { mbar_init(mbar_base, 1); mbar_init(mbar_base + 8, 1); }

        // register-resident slice
        float px[FPS_PPT], py[FPS_PPT], pz[FPS_PPT], pw[FPS_PPT], dist[FPS_PPT];
        unsigned gidx[FPS_PPT];
        bool valid[FPS_PPT];
#pragma unroll
        for (int j = 0; j < FPS_PPT; j++) {
            int li = t + j * FT;
            valid[j] = (li < FPS_PPC);
            int g = (int)cta * FPS_PPC + (valid[j] ? li : 0);
            float4 P = g_p4[g];
            px[j] = P.x; py[j] = P.y; pz[j] = P.z; pw[j] = P.w;
            dist[j] = 1e10f;
            gidx[j] = (unsigned)g;
        }
        const unsigned s_idx = cta * FPS_WARPS + (unsigned)warp;
        uint32_t rk[2] = {0, 0}, rm[2] = {0, 0};
        if (lane < FPS_CTAS) {
            uint32_t soff = s_idx * SLOT_BYTES;
            rk[0] = mapa_u32(slot_base + soff, (uint32_t)lane);
            rk[1] = mapa_u32(slot_base + FPS_SLOTS * SLOT_BYTES + soff, (uint32_t)lane);
            rm[0] = mapa_u32(mbar_base, (uint32_t)lane);
            rm[1] = mapa_u32(mbar_base + 8u, (uint32_t)lane);
        }

        // all mbarriers initialized before any st.async
        asm volatile("barrier.cluster.arrive.aligned;" ::: "memory");
        asm volatile("barrier.cluster.wait.aligned;" ::: "memory");

        float lx, ly, lz;
        {
            float4 P0 = g_p4[0];
            lx = P0.x; ly = P0.y; lz = P0.z;
            if (cta == 0 && t == 0) {
                g_q4[0] = P0;
                st_release_u32(&g_progress, 1u);
            }
            if (cta == 0 && t == 32) {
                out_np[0] = P0.x; out_np[1] = P0.y; out_np[2] = P0.z;
            }
        }
        unsigned ph0 = 0, ph1 = 0;

        for (int i = 1; i < Msamp; i++) {
            // --- update + per-thread argmax (uint order == float order, d>=0) ---
            unsigned bd = 0, bi = 0x7FFFFFFFu;
            float bx = 0.f, by = 0.f, bz = 0.f, bw = 0.f;
#pragma unroll
            for (int j = 0; j < FPS_PPT; j++) {
                float dx = __fsub_rn(px[j], lx);
                float dy = __fsub_rn(py[j], ly);
                float dz = __fsub_rn(pz[j], lz);
                float d  = __fadd_rn(__fadd_rn(__fmul_rn(dx, dx), __fmul_rn(dy, dy)),
                                     __fmul_rn(dz, dz));
                float nd = fminf(dist[j], d);
                dist[j] = nd;
                unsigned db = __float_as_uint(nd);
                if (valid[j] && db > bd) {
                    bd = db; bi = gidx[j];
                    bx = px[j]; by = py[j]; bz = pz[j]; bw = pw[j];
                }
            }
            unsigned dmax = __reduce_max_sync(0xFFFFFFFFu, bd);
            bool cand = (bd == dmax);
            unsigned idxmin = __reduce_min_sync(0xFFFFFFFFu, cand ? bi : 0xFFFFFFFFu);
            unsigned long long key =
                ((unsigned long long)dmax << 15) | ((32767u - idxmin) & 0x7FFFu);
            const int buf = i & 1;
            // winning lane broadcasts coords; lanes 0-7 ship triple to their CTA
            unsigned src_ballot = __ballot_sync(0xFFFFFFFFu, cand && bi == idxmin);
            int src = __ffs(src_ballot) - 1;
            float wx = __shfl_sync(0xFFFFFFFFu, bx, src);
            float wy = __shfl_sync(0xFFFFFFFFu, by, src);
            float wz = __shfl_sync(0xFFFFFFFFu, bz, src);
            float ww = __shfl_sync(0xFFFFFFFFu, bw, src);
            if (lane < FPS_CTAS) {
                uint32_t rs = rk[buf], rmm = rm[buf];
                st_async_u64(rs,      key,            rmm);
                st_async_u64(rs + 8,  pack2f(wx, wy), rmm);
                st_async_u64(rs + 16, pack2f(wz, ww), rmm);
            }
            if (t == 0) mbar_expect_tx(mbar_base + 8u * (unsigned)buf,
                                       FPS_SLOTS * SLOT_BYTES);

            mbar_wait_parity(mbar_base + 8u * (unsigned)buf, buf ? ph1 : ph0);
            if (buf) ph1 ^= 1; else ph0 ^= 1;

            unsigned long long wkey;
            int sl = slot_reduce(s_slots[buf], lane, wkey);
            unsigned long long wxy = s_slots[buf][sl * 3 + 1];
            unsigned long long wzw = s_slots[buf][sl * 3 + 2];
            lx = __uint_as_float((unsigned)wxy);
            ly = __uint_as_float((unsigned)(wxy >> 32));
            lz = __uint_as_float((unsigned)wzw);
            if (cta == 0 && t == 0) {
                float w2 = __uint_as_float((unsigned)(wzw >> 32));
                g_q4[i] = make_float4(lx, ly, lz, w2);
                st_release_u32(&g_progress, (unsigned)i + 1u);
            }
            if (cta == 0 && t == 32) {
                out_np[3 * i] = lx; out_np[3 * i + 1] = ly; out_np[3 * i + 2] = lz;
            }
        }
        // trailing cluster barrier: no CTA exits with peers' st.async in flight
        asm volatile("barrier.cluster.arrive.aligned;" ::: "memory");
        asm volatile("barrier.cluster.wait.aligned;" ::: "memory");
        return;
    }

    // ======================= polling kNN consumers =======================
    const int jb = blockIdx.x - FPS_CTAS;
    unsigned long long* cand = dyn_smem + warp * 80;
    for (int q = jb * 8 + warp; q < Msamp; q += KNN_WARPS_TOT) {
        const unsigned need = (unsigned)q + 1u;
        unsigned pr = ld_acq_u32(&g_progress);
        while (pr < need) { __nanosleep(512); pr = ld_acq_u32(&g_progress); }
        float4 Q = ld_acq_f4(&g_q4[q]);
        knn_query(Q, q, lane, cand);
    }
}

// ---------------- gather + linear; store per-(m,c) max/min of h + BN partials ----------------
__global__ __launch_bounds__(128) void gemm_kernel(const float* __restrict__ x,
                                                   const float* __restrict__ W) {
    __shared__ float sW[FDIM * COUT];
    __shared__ float sF[KNN][FDIM + 1];
    const int m = blockIdx.x, t = threadIdx.x;

    for (int i = t; i < FDIM * COUT; i += 128) sW[i] = W[i];
    const float4 Q = g_q4[m];
    for (int e = t; e < KNN * FDIM; e += 128) {
        int r = e / FDIM, j = e - r * FDIM;
        int n = g_nidx[m * KNN + r];
        float v;
        if (j < 3) {
            float4 P = g_p4[n];
            v = (j == 0) ? __fsub_rn(P.x, Q.x) : (j == 1) ? __fsub_rn(P.y, Q.y)
                                                          : __fsub_rn(P.z, Q.z);
        } else {
            v = __ldg(&x[n * CIN + (j - 3)]);
        }
        sF[r][j] = v;
    }
    __syncthreads();

    float acc[KNN];
#pragma unroll
    for (int r = 0; r < KNN; r++) acc[r] = 0.0f;
#pragma unroll 1
    for (int j = 0; j < FDIM; j++) {
        float wv = sW[j * COUT + t];
#pragma unroll
        for (int r = 0; r < KNN; r++) acc[r] = fmaf(sF[r][j], wv, acc[r]);
    }
    float s1 = 0.0f, s2 = 0.0f;
    float mx = acc[0], mn = acc[0];
#pragma unroll
    for (int r = 0; r < KNN; r++) {
        s1 += acc[r];
        s2 = fmaf(acc[r], acc[r], s2);
        mx = fmaxf(mx, acc[r]);
        mn = fminf(mn, acc[r]);
    }
    g_maxh[m * COUT + t] = mx;
    g_minh[m * COUT + t] = mn;
    g_ps [m * COUT + t] = s1;
    g_pss[m * COUT + t] = s2;
}

// ---------------- deterministic BN stats reduction ----------------
__global__ __launch_bounds__(256) void stats_kernel() {
    __shared__ float s1[256], s2[256];
    const int c = blockIdx.x, t = threadIdx.x;
    float a = 0.0f, b = 0.0f;
    for (int m = t; m < Msamp; m += 256) {
        a += g_ps [m * COUT + c];
        b += g_pss[m * COUT + c];
    }
    s1[t] = a; s2[t] = b;
    __syncthreads();
    for (int o = 128; o; o >>= 1) {
        if (t < o) { s1[t] += s1[t + o]; s2[t] += s2[t + o]; }
        __syncthreads();
    }
    if (t == 0) {
        const float inv_n = 1.0f / (float)(Msamp * KNN);
        float mean = s1[0] * inv_n;
        float var  = fmaxf(s2[0] * inv_n - mean * mean, 0.0f);
        g_mean[c] = mean;
        g_rstd[c] = rsqrtf(var + BN_EPS);
    }
}

// ---------------- BN + ReLU + maxpool (exact via per-channel monotonicity) ----------------
__global__ __launch_bounds__(128) void final_kernel(const float* __restrict__ gamma,
                                                    const float* __restrict__ beta,
                                                    float* __restrict__ out_x,
                                                    float* __restrict__ out_no) {
    const int m = blockIdx.x, c = threadIdx.x;
    const float mean = g_mean[c], inv = g_rstd[c];
    const float gm = __ldg(&gamma[c]), bt = __ldg(&beta[c]);
    float h = (gm >= 0.0f) ? g_maxh[m * COUT + c] : g_minh[m * COUT + c];
    float y = fmaxf((h - mean) * inv * gm + bt, 0.0f);
    out_x[m * COUT + c] = y;
    if (out_no != nullptr && m == 0 && c == 0) *out_no = (float)Msamp;
}

// ---------------- launch ----------------
extern "C" void kernel_launch(void* const* d_in, const int* in_sizes, int n_in,
                              void* d_out, int out_size) {
    const float* p     = (const float*)d_in[0];
    const float* x     = (const float*)d_in[1];
    const float* W     = (const float*)d_in[3];
    const float* gamma = (const float*)d_in[4];
    const float* beta  = (const float*)d_in[5];
    float* out = (float*)d_out;

    const int np_elems = Msamp * 3;
    const int x_elems  = Msamp * COUT;

    float* np_dst = out;
    float* x_dst  = out + np_elems;
    float* no_dst = nullptr;
    if (out_size >= np_elems + x_elems + 1) {
        no_dst = out + np_elems + x_elems;
    } else if (out_size == x_elems) {
        float* scr; cudaGetSymbolAddress((void**)&scr, g_np_scratch);
        np_dst = scr;
        x_dst  = out;
    }

    cudaFuncSetAttribute(fused_kernel, cudaFuncAttributeMaxDynamicSharedMemorySize,
                         DYN_SMEM);

    pack_kernel <<<(Npts + 255) / 256, 256>>>(p);
    fused_kernel<<<GRID_FUSED, FT, DYN_SMEM>>>(np_dst);
    gemm_kernel <<<Msamp, 128>>>(x, W);
    stats_kernel<<<COUT, 256>>>();
    final_kernel<<<Msamp, 128>>>(gamma, beta, x_dst, no_dst);
}

// round 10
// speedup vs baseline: 1.1866x; 1.1866x over previous
#include <cuda_runtime.h>
#include <cstdint>

#define Npts   20000
#define Msamp  5000
#define KNN    16
#define CIN    64
#define COUT   128
#define FDIM   (3 + CIN)          // 67
#define BN_EPS 1e-5f

// FPS cluster config (R6-verified comm core + writer warp)
#define FPS_CTAS    8
#define OWN_T       256                       // sender threads (warps 0-7)
#define FT          288                       // + writer warp (warp 8)
#define FPS_WARPS   8
#define FPS_SLOTS   (FPS_CTAS * FPS_WARPS)    // 64
#define FPS_PPC     (Npts / FPS_CTAS)         // 2500
#define FPS_PPT     10
#define SLOT_BYTES  24
// fused-grid knn consumers: 17 clusters total -> always resident in one wave
#define KNN_BLOCKS    128
#define GRID_FUSED    (FPS_CTAS + KNN_BLOCKS) // 136
#define KNN_WARPS_TOT (KNN_BLOCKS * 9)        // 1152
#define DYN_SMEM      (120 * 1024)            // forces 1 block/SM

// ---------------- device scratch (no allocs allowed) ----------------
__device__ float4   g_p4[Npts];
__device__ float4   g_q4[Msamp];
__device__ unsigned g_progress;               // #valid q4 entries (monotone per run)
__device__ int      g_nidx[Msamp * KNN];
__device__ float    g_maxh[Msamp * COUT];
__device__ float    g_minh[Msamp * COUT];
__device__ float    g_ps [Msamp * COUT];
__device__ float    g_pss[Msamp * COUT];
__device__ float    g_mean[COUT];
__device__ float    g_rstd[COUT];
__device__ float    g_np_scratch[Msamp * 3];

// ---------------- PTX helpers ----------------
__device__ __forceinline__ uint32_t smem_u32(const void* p) {
    uint32_t a;
    asm("{ .reg .u64 t; cvta.to.shared.u64 t, %1; cvt.u32.u64 %0, t; }" : "=r"(a) : "l"(p));
    return a;
}
__device__ __forceinline__ uint32_t mapa_u32(uint32_t local_addr, uint32_t rank) {
    uint32_t r;
    asm("mapa.shared::cluster.u32 %0, %1, %2;" : "=r"(r) : "r"(local_addr), "r"(rank));
    return r;
}
__device__ __forceinline__ void st_async_u64(uint32_t raddr, unsigned long long v,
                                             uint32_t rmbar) {
    asm volatile("st.async.shared::cluster.mbarrier::complete_tx::bytes.b64 [%0], %1, [%2];"
                 :: "r"(raddr), "l"(v), "r"(rmbar) : "memory");
}
__device__ __forceinline__ void mbar_init(uint32_t mbar, uint32_t cnt) {
    asm volatile("mbarrier.init.shared.b64 [%0], %1;" :: "r"(mbar), "r"(cnt) : "memory");
}
__device__ __forceinline__ void mbar_expect_tx(uint32_t mbar, uint32_t bytes) {
    asm volatile("mbarrier.arrive.expect_tx.shared.b64 _, [%0], %1;"
                 :: "r"(mbar), "r"(bytes) : "memory");
}
__device__ __forceinline__ void mbar_arrive_remote(uint32_t rmbar) {
    asm volatile("mbarrier.arrive.shared::cluster.b64 _, [%0];"
                 :: "r"(rmbar) : "memory");
}
__device__ __forceinline__ void mbar_wait_parity(uint32_t mbar, uint32_t ph) {
    uint32_t done = 0;
    while (!done) {
        asm volatile(
            "{\n\t.reg .pred p;\n\t"
            "mbarrier.try_wait.parity.acquire.cluster.shared::cta.b64 p, [%1], %2, 0x989680;\n\t"
            "selp.b32 %0, 1, 0, p;\n\t}"
            : "=r"(done) : "r"(mbar), "r"(ph) : "memory");
    }
}
__device__ __forceinline__ unsigned long long pack2f(float a, float b) {
    return ((unsigned long long)__float_as_uint(b) << 32) | __float_as_uint(a);
}
__device__ __forceinline__ void st_release_u32(unsigned* p, unsigned v) {
    asm volatile("st.global.release.gpu.u32 [%0], %1;" :: "l"(p), "r"(v) : "memory");
}
__device__ __forceinline__ unsigned ld_acq_u32(const unsigned* p) {
    unsigned v;
    asm volatile("ld.global.acquire.gpu.u32 %0, [%1];" : "=r"(v) : "l"(p) : "memory");
    return v;
}
__device__ __forceinline__ float4 ld_acq_f4(const float4* p) {
    float4 v;
    asm volatile("ld.global.acquire.gpu.v4.f32 {%0,%1,%2,%3}, [%4];"
                 : "=f"(v.x), "=f"(v.y), "=f"(v.z), "=f"(v.w) : "l"(p) : "memory");
    return v;
}

// slot argmax: winning slot index + key (all lanes), tie -> lowest global idx
__device__ __forceinline__ int slot_reduce(const unsigned long long* slots, int lane,
                                           unsigned long long& wkey) {
    unsigned long long v0 = slots[lane * 3];
    unsigned long long v1 = slots[(lane + 32) * 3];
    unsigned d0 = (unsigned)(v0 >> 15), d1 = (unsigned)(v1 >> 15);
    unsigned dg = __reduce_max_sync(0xFFFFFFFFu, d0 > d1 ? d0 : d1);
    unsigned l = 0;
    if (d0 == dg) l = (unsigned)v0 & 0x7FFFu;
    if (d1 == dg) { unsigned l1 = (unsigned)v1 & 0x7FFFu; if (l1 > l) l = l1; }
    unsigned lg = __reduce_max_sync(0xFFFFFFFFu, l);
    wkey = ((unsigned long long)dg << 15) | lg;
    unsigned b0 = __ballot_sync(0xFFFFFFFFu, v0 == wkey);
    int sl;
    if (b0) sl = __ffs(b0) - 1;
    else {
        unsigned b1 = __ballot_sync(0xFFFFFFFFu, v1 == wkey);
        sl = 32 + __ffs(b1) - 1;
    }
    return sl;
}

// ---------------- pack ----------------
__global__ void pack_kernel(const float* __restrict__ p) {
    int i = blockIdx.x * blockDim.x + threadIdx.x;
    if (i < Npts) {
        float x = p[3 * i], y = p[3 * i + 1], z = p[3 * i + 2];
        float pp = __fadd_rn(__fadd_rn(__fmul_rn(x, x), __fmul_rn(y, y)), __fmul_rn(z, z));
        g_p4[i] = make_float4(x, y, z, pp);
    }
}

// ---------------- kNN warp scan (verified bit-exact) ----------------
#define INFKEY 0xFFFFFFFFFFFFFFFFull

__device__ __forceinline__ void knn_merge(unsigned long long* cand, int lane,
                                          unsigned long long& cur,
                                          unsigned long long& thr, int& cnt) {
    if (lane < 16) cand[64 + lane] = cur;
#pragma unroll
    for (int s = lane; s < 64; s += 32) if (s >= cnt) cand[s] = INFKEY;
    __syncwarp();
    unsigned long long picked = INFKEY, last = INFKEY;
#pragma unroll 1
    for (int r = 0; r < 16; r++) {
        unsigned long long a = cand[lane];
        unsigned long long b = cand[lane + 32];
        unsigned long long c = (lane < 16) ? cand[64 + lane] : INFKEY;
        unsigned long long v = a < b ? a : b;
        v = v < c ? v : c;
#pragma unroll
        for (int off = 16; off; off >>= 1) {
            unsigned long long o = __shfl_down_sync(0xFFFFFFFFu, v, off);
            if (o < v) v = o;
        }
        v = __shfl_sync(0xFFFFFFFFu, v, 0);
        if (a == v)                       cand[lane]      = INFKEY;
        else if (b == v)                  cand[lane + 32] = INFKEY;
        else if (lane < 16 && c == v)     cand[64 + lane] = INFKEY;
        __syncwarp();
        if (lane == r) picked = v;
        last = v;
    }
    cur = picked; thr = last; cnt = 0;
    __syncwarp();
}

__device__ __forceinline__ void knn_query(const float4 Q, int q, int lane,
                                          unsigned long long* cand) {
    unsigned long long cur = INFKEY, thr = INFKEY;
    int cnt = 0;
#pragma unroll 1
    for (int s = 0; s < Npts / 32; s++) {
        int idx = lane + 32 * s;
        float4 P = __ldg(&g_p4[idx]);
        float dot = __fmaf_rn(Q.z, P.z, __fmaf_rn(Q.y, P.y, __fmul_rn(Q.x, P.x)));
        float d = __fadd_rn(__fsub_rn(Q.w, __fmul_rn(2.0f, dot)), P.w);
        unsigned ub = __float_as_uint(d);
        ub ^= (ub >> 31) ? 0xFFFFFFFFu : 0x80000000u;
        unsigned long long k = ((unsigned long long)ub << 32) | (unsigned)idx;
        bool pred = k < thr;
        unsigned bal = __ballot_sync(0xFFFFFFFFu, pred);
        if (pred) {
            int pos = cnt + __popc(bal & ((1u << lane) - 1u));
            cand[pos] = k;
        }
        cnt += __popc(bal);
        if (cnt >= 32) knn_merge(cand, lane, cur, thr, cnt);
    }
    if (cnt > 0) knn_merge(cand, lane, cur, thr, cnt);
    if (lane < 16) g_nidx[q * KNN + lane] = (int)(unsigned)(cur & 0xFFFFFFFFull);
}

// ---------------- fused: FPS cluster (blocks 0-7) + polling kNN ----------------
__global__ void __cluster_dims__(FPS_CTAS, 1, 1) __launch_bounds__(FT, 1)
fused_kernel(float* __restrict__ out_np) {
    extern __shared__ unsigned long long dyn_smem[];
    __shared__ unsigned long long s_slots[2][FPS_SLOTS * 3];
    __shared__ unsigned long long s_mbar[2];
    const int t = threadIdx.x, warp = t >> 5, lane = t & 31;

    if (blockIdx.x < FPS_CTAS) {
        uint32_t cta;
        asm("mov.u32 %0, %%cluster_ctarank;" : "=r"(cta));
        const uint32_t slot_base = smem_u32(&s_slots[0][0]);
        const uint32_t mbar_base = smem_u32(&s_mbar[0]);
        // arrive count 2: t0's expect_tx arrival + writer's remote arrival
        if (t == 0) { mbar_init(mbar_base, 2); mbar_init(mbar_base + 8, 2); }

        // all mbarriers initialized before any st.async / arrive
        asm volatile("barrier.cluster.arrive.aligned;" ::: "memory");
        asm volatile("barrier.cluster.wait.aligned;" ::: "memory");

        if (warp < FPS_WARPS) {
            // ======================= senders (R6 core, NO global ops) =======================
            float px[FPS_PPT], py[FPS_PPT], pz[FPS_PPT], pw[FPS_PPT], dist[FPS_PPT];
            unsigned gidx[FPS_PPT];
            bool valid[FPS_PPT];
#pragma unroll
            for (int j = 0; j < FPS_PPT; j++) {
                int li = t + j * OWN_T;
                valid[j] = (li < FPS_PPC);
                int g = (int)cta * FPS_PPC + (valid[j] ? li : 0);
                float4 P = g_p4[g];
                px[j] = P.x; py[j] = P.y; pz[j] = P.z; pw[j] = P.w;
                dist[j] = 1e10f;
                gidx[j] = (unsigned)g;
            }
            const unsigned s_idx = cta * FPS_WARPS + (unsigned)warp;
            uint32_t rk[2] = {0, 0}, rm[2] = {0, 0};
            if (lane < FPS_CTAS) {
                uint32_t soff = s_idx * SLOT_BYTES;
                rk[0] = mapa_u32(slot_base + soff, (uint32_t)lane);
                rk[1] = mapa_u32(slot_base + FPS_SLOTS * SLOT_BYTES + soff, (uint32_t)lane);
                rm[0] = mapa_u32(mbar_base, (uint32_t)lane);
                rm[1] = mapa_u32(mbar_base + 8u, (uint32_t)lane);
            }
            float lx, ly, lz;
            { float4 P0 = g_p4[0]; lx = P0.x; ly = P0.y; lz = P0.z; }
            unsigned ph0 = 0, ph1 = 0;

            for (int i = 1; i < Msamp; i++) {
                unsigned bd = 0, bi = 0x7FFFFFFFu;
                float bx = 0.f, by = 0.f, bz = 0.f, bw = 0.f;
#pragma unroll
                for (int j = 0; j < FPS_PPT; j++) {
                    float dx = __fsub_rn(px[j], lx);
                    float dy = __fsub_rn(py[j], ly);
                    float dz = __fsub_rn(pz[j], lz);
                    float d  = __fadd_rn(__fadd_rn(__fmul_rn(dx, dx), __fmul_rn(dy, dy)),
                                         __fmul_rn(dz, dz));
                    float nd = fminf(dist[j], d);
                    dist[j] = nd;
                    unsigned db = __float_as_uint(nd);
                    if (valid[j] && db > bd) {
                        bd = db; bi = gidx[j];
                        bx = px[j]; by = py[j]; bz = pz[j]; bw = pw[j];
                    }
                }
                unsigned dmax = __reduce_max_sync(0xFFFFFFFFu, bd);
                bool cand = (bd == dmax);
                unsigned idxmin = __reduce_min_sync(0xFFFFFFFFu, cand ? bi : 0xFFFFFFFFu);
                unsigned long long key =
                    ((unsigned long long)dmax << 15) | ((32767u - idxmin) & 0x7FFFu);
                const int buf = i & 1;
                unsigned src_ballot = __ballot_sync(0xFFFFFFFFu, cand && bi == idxmin);
                int src = __ffs(src_ballot) - 1;
                float wx = __shfl_sync(0xFFFFFFFFu, bx, src);
                float wy = __shfl_sync(0xFFFFFFFFu, by, src);
                float wz = __shfl_sync(0xFFFFFFFFu, bz, src);
                float ww = __shfl_sync(0xFFFFFFFFu, bw, src);
                if (lane < FPS_CTAS) {
                    uint32_t rs = rk[buf], rmm = rm[buf];
                    st_async_u64(rs,      key,            rmm);
                    st_async_u64(rs + 8,  pack2f(wx, wy), rmm);
                    st_async_u64(rs + 16, pack2f(wz, ww), rmm);
                }
                if (t == 0) mbar_expect_tx(mbar_base + 8u * (unsigned)buf,
                                           FPS_SLOTS * SLOT_BYTES);

                mbar_wait_parity(mbar_base + 8u * (unsigned)buf, buf ? ph1 : ph0);
                if (buf) ph1 ^= 1; else ph0 ^= 1;

                unsigned long long wkey;
                int sl = slot_reduce(s_slots[buf], lane, wkey);
                unsigned long long wxy = s_slots[buf][sl * 3 + 1];
                unsigned long long wzw = s_slots[buf][sl * 3 + 2];
                lx = __uint_as_float((unsigned)wxy);
                ly = __uint_as_float((unsigned)(wxy >> 32));
                lz = __uint_as_float((unsigned)wzw);
            }
        } else if (cta == 0) {
            // ======================= writer warp (CTA0 warp 8) =======================
            uint32_t ra0 = 0, ra1 = 0;
            if (lane < FPS_CTAS) {
                ra0 = mapa_u32(mbar_base,      (uint32_t)lane);
                ra1 = mapa_u32(mbar_base + 8u, (uint32_t)lane);
            }
            // publish q0 and arrive for phase 1 (buf 1)
            if (lane == 0) {
                float4 P0 = g_p4[0];
                g_q4[0] = P0;
                st_release_u32(&g_progress, 1u);
            }
            if (lane == 1) {
                float4 P0 = g_p4[0];
                out_np[0] = P0.x; out_np[1] = P0.y; out_np[2] = P0.z;
            }
            if (lane < FPS_CTAS) mbar_arrive_remote(ra1);

            unsigned ph0 = 0, ph1 = 0;
            for (int i = 1; i < Msamp; i++) {
                const int buf = i & 1;
                mbar_wait_parity(mbar_base + 8u * (unsigned)buf, buf ? ph1 : ph0);
                if (buf) ph1 ^= 1; else ph0 ^= 1;

                unsigned long long wkey;
                int sl = slot_reduce(s_slots[buf], lane, wkey);
                unsigned long long wxy = s_slots[buf][sl * 3 + 1];
                unsigned long long wzw = s_slots[buf][sl * 3 + 2];
                float wx = __uint_as_float((unsigned)wxy);
                float wy = __uint_as_float((unsigned)(wxy >> 32));
                float wz = __uint_as_float((unsigned)wzw);
                float ww = __uint_as_float((unsigned)(wzw >> 32));
                if (lane == 0) {
                    g_q4[i] = make_float4(wx, wy, wz, ww);
                    st_release_u32(&g_progress, (unsigned)i + 1u);
                }
                if (lane == 1) {
                    out_np[3 * i] = wx; out_np[3 * i + 1] = wy; out_np[3 * i + 2] = wz;
                }
                // arrive for NEXT phase only after this buffer's reads are done:
                // bounds sender overwrites provably behind writer reads
                if (i + 1 < Msamp && lane < FPS_CTAS)
                    mbar_arrive_remote(((i + 1) & 1) ? ra1 : ra0);
            }
        }
        // trailing cluster barrier: no CTA exits with peers' st.async in flight
        asm volatile("barrier.cluster.arrive.aligned;" ::: "memory");
        asm volatile("barrier.cluster.wait.aligned;" ::: "memory");
        return;
    }

    // ======================= polling kNN consumers =======================
    const int jb = blockIdx.x - FPS_CTAS;
    unsigned long long* cand = dyn_smem + warp * 80;
    for (int q = jb * 9 + warp; q < Msamp; q += KNN_WARPS_TOT) {
        const unsigned need = (unsigned)q + 1u;
        unsigned pr = ld_acq_u32(&g_progress);
        while (pr < need) {
            unsigned deficit = need - pr;
            __nanosleep(deficit > 16u ? 8192u : deficit * 512u);
            pr = ld_acq_u32(&g_progress);
        }
        float4 Q = ld_acq_f4(&g_q4[q]);
        knn_query(Q, q, lane, cand);
    }
}

// ---------------- gather + linear; store per-(m,c) max/min of h + BN partials ----------------
__global__ __launch_bounds__(128) void gemm_kernel(const float* __restrict__ x,
                                                   const float* __restrict__ W) {
    __shared__ float sW[FDIM * COUT];
    __shared__ float sF[KNN][FDIM + 1];
    const int m = blockIdx.x, t = threadIdx.x;

    for (int i = t; i < FDIM * COUT; i += 128) sW[i] = W[i];
    const float4 Q = g_q4[m];
    for (int e = t; e < KNN * FDIM; e += 128) {
        int r = e / FDIM, j = e - r * FDIM;
        int n = g_nidx[m * KNN + r];
        float v;
        if (j < 3) {
            float4 P = g_p4[n];
            v = (j == 0) ? __fsub_rn(P.x, Q.x) : (j == 1) ? __fsub_rn(P.y, Q.y)
                                                          : __fsub_rn(P.z, Q.z);
        } else {
            v = __ldg(&x[n * CIN + (j - 3)]);
        }
        sF[r][j] = v;
    }
    __syncthreads();

    float acc[KNN];
#pragma unroll
    for (int r = 0; r < KNN; r++) acc[r] = 0.0f;
#pragma unroll 1
    for (int j = 0; j < FDIM; j++) {
        float wv = sW[j * COUT + t];
#pragma unroll
        for (int r = 0; r < KNN; r++) acc[r] = fmaf(sF[r][j], wv, acc[r]);
    }
    float s1 = 0.0f, s2 = 0.0f;
    float mx = acc[0], mn = acc[0];
#pragma unroll
    for (int r = 0; r < KNN; r++) {
        s1 += acc[r];
        s2 = fmaf(acc[r], acc[r], s2);
        mx = fmaxf(mx, acc[r]);
        mn = fminf(mn, acc[r]);
    }
    g_maxh[m * COUT + t] = mx;
    g_minh[m * COUT + t] = mn;
    g_ps [m * COUT + t] = s1;
    g_pss[m * COUT + t] = s2;
}

// ---------------- deterministic BN stats reduction ----------------
__global__ __launch_bounds__(256) void stats_kernel() {
    __shared__ float s1[256], s2[256];
    const int c = blockIdx.x, t = threadIdx.x;
    float a = 0.0f, b = 0.0f;
    for (int m = t; m < Msamp; m += 256) {
        a += g_ps [m * COUT + c];
        b += g_pss[m * COUT + c];
    }
    s1[t] = a; s2[t] = b;
    __syncthreads();
    for (int o = 128; o; o >>= 1) {
        if (t < o) { s1[t] += s1[t + o]; s2[t] += s2[t + o]; }
        __syncthreads();
    }
    if (t == 0) {
        const float inv_n = 1.0f / (float)(Msamp * KNN);
        float mean = s1[0] * inv_n;
        float var  = fmaxf(s2[0] * inv_n - mean * mean, 0.0f);
        g_mean[c] = mean;
        g_rstd[c] = rsqrtf(var + BN_EPS);
    }
}

// ---------------- BN + ReLU + maxpool (exact via per-channel monotonicity) ----------------
__global__ __launch_bounds__(128) void final_kernel(const float* __restrict__ gamma,
                                                    const float* __restrict__ beta,
                                                    float* __restrict__ out_x,
                                                    float* __restrict__ out_no) {
    const int m = blockIdx.x, c = threadIdx.x;
    const float mean = g_mean[c], inv = g_rstd[c];
    const float gm = __ldg(&gamma[c]), bt = __ldg(&beta[c]);
    float h = (gm >= 0.0f) ? g_maxh[m * COUT + c] : g_minh[m * COUT + c];
    float y = fmaxf((h - mean) * inv * gm + bt, 0.0f);
    out_x[m * COUT + c] = y;
    if (out_no != nullptr && m == 0 && c == 0) *out_no = (float)Msamp;
}

// ---------------- launch ----------------
extern "C" void kernel_launch(void* const* d_in, const int* in_sizes, int n_in,
                              void* d_out, int out_size) {
    const float* p     = (const float*)d_in[0];
    const float* x     = (const float*)d_in[1];
    const float* W     = (const float*)d_in[3];
    const float* gamma = (const float*)d_in[4];
    const float* beta  = (const float*)d_in[5];
    float* out = (float*)d_out;

    const int np_elems = Msamp * 3;
    const int x_elems  = Msamp * COUT;

    float* np_dst = out;
    float* x_dst  = out + np_elems;
    float* no_dst = nullptr;
    if (out_size >= np_elems + x_elems + 1) {
        no_dst = out + np_elems + x_elems;
    } else if (out_size == x_elems) {
        float* scr; cudaGetSymbolAddress((void**)&scr, g_np_scratch);
        np_dst = scr;
        x_dst  = out;
    }

    cudaFuncSetAttribute(fused_kernel, cudaFuncAttributeMaxDynamicSharedMemorySize,
                         DYN_SMEM);

    pack_kernel <<<(Npts + 255) / 256, 256>>>(p);
    fused_kernel<<<GRID_FUSED, FT, DYN_SMEM>>>(np_dst);
    gemm_kernel <<<Msamp, 128>>>(x, W);
    stats_kernel<<<COUT, 256>>>();
    final_kernel<<<Msamp, 128>>>(gamma, beta, x_dst, no_dst);
}

// round 11
// speedup vs baseline: 1.3973x; 1.1776x over previous
#include <cuda_runtime.h>
#include <cstdint>

#define Npts   20000
#define Msamp  5000
#define KNN    16
#define CIN    64
#define COUT   128
#define FDIM   (3 + CIN)          // 67
#define BN_EPS 1e-5f

// FPS cluster config (R6-verified core)
#define FPS_CTAS    8
#define FT          256
#define FPS_WARPS   8
#define FPS_SLOTS   (FPS_CTAS * FPS_WARPS)    // 64
#define FPS_PPC     (Npts / FPS_CTAS)         // 2500
#define FPS_PPT     10
#define SLOT_BYTES  24
// fused-grid knn consumers: 17 clusters total -> always resident in one wave
#define KNN_BLOCKS    128
#define GRID_FUSED    (FPS_CTAS + KNN_BLOCKS) // 136
#define KNN_WARPS_TOT (KNN_BLOCKS * 8)        // 1024
#define DYN_SMEM      (120 * 1024)            // forces 1 block/SM

#define MARKW 0xFFC00000u                     // negative quiet NaN: impossible |q|^2

// gemm batching
#define GM 2

// ---------------- device scratch (no allocs allowed) ----------------
__device__ float4   g_p4[Npts];
__device__ float4   g_q4[Msamp];
__device__ int      g_nidx[Msamp * KNN];
__device__ float    g_maxh[Msamp * COUT];
__device__ float    g_minh[Msamp * COUT];
__device__ float    g_ps [Msamp * COUT];
__device__ float    g_pss[Msamp * COUT];
__device__ float    g_mean[COUT];
__device__ float    g_rstd[COUT];
__device__ float    g_np_scratch[Msamp * 3];

// ---------------- PTX helpers ----------------
__device__ __forceinline__ uint32_t smem_u32(const void* p) {
    uint32_t a;
    asm("{ .reg .u64 t; cvta.to.shared.u64 t, %1; cvt.u32.u64 %0, t; }" : "=r"(a) : "l"(p));
    return a;
}
__device__ __forceinline__ uint32_t mapa_u32(uint32_t local_addr, uint32_t rank) {
    uint32_t r;
    asm("mapa.shared::cluster.u32 %0, %1, %2;" : "=r"(r) : "r"(local_addr), "r"(rank));
    return r;
}
__device__ __forceinline__ void st_async_u64(uint32_t raddr, unsigned long long v,
                                             uint32_t rmbar) {
    asm volatile("st.async.shared::cluster.mbarrier::complete_tx::bytes.b64 [%0], %1, [%2];"
                 :: "r"(raddr), "l"(v), "r"(rmbar) : "memory");
}
__device__ __forceinline__ void mbar_init(uint32_t mbar, uint32_t cnt) {
    asm volatile("mbarrier.init.shared.b64 [%0], %1;" :: "r"(mbar), "r"(cnt) : "memory");
}
__device__ __forceinline__ void mbar_expect_tx(uint32_t mbar, uint32_t bytes) {
    asm volatile("mbarrier.arrive.expect_tx.shared.b64 _, [%0], %1;"
                 :: "r"(mbar), "r"(bytes) : "memory");
}
__device__ __forceinline__ void mbar_wait_parity(uint32_t mbar, uint32_t ph) {
    uint32_t done = 0;
    while (!done) {
        asm volatile(
            "{\n\t.reg .pred p;\n\t"
            "mbarrier.try_wait.parity.acquire.cluster.shared::cta.b64 p, [%1], %2, 0x989680;\n\t"
            "selp.b32 %0, 1, 0, p;\n\t}"
            : "=r"(done) : "r"(mbar), "r"(ph) : "memory");
    }
}
__device__ __forceinline__ unsigned long long pack2f(float a, float b) {
    return ((unsigned long long)__float_as_uint(b) << 32) | __float_as_uint(a);
}
__device__ __forceinline__ void st_global_f4(float4* p, float a, float b, float c, float d) {
    asm volatile("st.global.v4.f32 [%0], {%1, %2, %3, %4};"
                 :: "l"(p), "f"(a), "f"(b), "f"(c), "f"(d) : "memory");
}
__device__ __forceinline__ float4 ld_vol_f4(const float4* p) {
    float4 v;
    asm volatile("ld.volatile.global.v4.f32 {%0,%1,%2,%3}, [%4];"
                 : "=f"(v.x), "=f"(v.y), "=f"(v.z), "=f"(v.w) : "l"(p) : "memory");
    return v;
}

// slot argmax: winning slot index + key (all lanes), tie -> lowest global idx
__device__ __forceinline__ int slot_reduce(const unsigned long long* slots, int lane,
                                           unsigned long long& wkey) {
    unsigned long long v0 = slots[lane * 3];
    unsigned long long v1 = slots[(lane + 32) * 3];
    unsigned d0 = (unsigned)(v0 >> 15), d1 = (unsigned)(v1 >> 15);
    unsigned dg = __reduce_max_sync(0xFFFFFFFFu, d0 > d1 ? d0 : d1);
    unsigned l = 0;
    if (d0 == dg) l = (unsigned)v0 & 0x7FFFu;
    if (d1 == dg) { unsigned l1 = (unsigned)v1 & 0x7FFFu; if (l1 > l) l = l1; }
    unsigned lg = __reduce_max_sync(0xFFFFFFFFu, l);
    wkey = ((unsigned long long)dg << 15) | lg;
    unsigned b0 = __ballot_sync(0xFFFFFFFFu, v0 == wkey);
    int sl;
    if (b0) sl = __ffs(b0) - 1;
    else {
        unsigned b1 = __ballot_sync(0xFFFFFFFFu, v1 == wkey);
        sl = 32 + __ffs(b1) - 1;
    }
    return sl;
}

// ---------------- pack ----------------
__global__ void pack_kernel(const float* __restrict__ p) {
    int i = blockIdx.x * blockDim.x + threadIdx.x;
    if (i < Npts) {
        float x = p[3 * i], y = p[3 * i + 1], z = p[3 * i + 2];
        float pp = __fadd_rn(__fadd_rn(__fmul_rn(x, x), __fmul_rn(y, y)), __fmul_rn(z, z));
        g_p4[i] = make_float4(x, y, z, pp);
    }
}

// ---------------- marker: poison q4.w so consumers can detect THIS run's writes ----------------
__global__ void marker_kernel() {
    int i = blockIdx.x * blockDim.x + threadIdx.x;
    if (i < Msamp) reinterpret_cast<unsigned*>(&g_q4[i])[3] = MARKW;
}

// ---------------- kNN warp scan (verified bit-exact) ----------------
#define INFKEY 0xFFFFFFFFFFFFFFFFull

__device__ __forceinline__ void knn_merge(unsigned long long* cand, int lane,
                                          unsigned long long& cur,
                                          unsigned long long& thr, int& cnt) {
    if (lane < 16) cand[64 + lane] = cur;
#pragma unroll
    for (int s = lane; s < 64; s += 32) if (s >= cnt) cand[s] = INFKEY;
    __syncwarp();
    unsigned long long picked = INFKEY, last = INFKEY;
#pragma unroll 1
    for (int r = 0; r < 16; r++) {
        unsigned long long a = cand[lane];
        unsigned long long b = cand[lane + 32];
        unsigned long long c = (lane < 16) ? cand[64 + lane] : INFKEY;
        unsigned long long v = a < b ? a : b;
        v = v < c ? v : c;
#pragma unroll
        for (int off = 16; off; off >>= 1) {
            unsigned long long o = __shfl_down_sync(0xFFFFFFFFu, v, off);
            if (o < v) v = o;
        }
        v = __shfl_sync(0xFFFFFFFFu, v, 0);
        if (a == v)                       cand[lane]      = INFKEY;
        else if (b == v)                  cand[lane + 32] = INFKEY;
        else if (lane < 16 && c == v)     cand[64 + lane] = INFKEY;
        __syncwarp();
        if (lane == r) picked = v;
        last = v;
    }
    cur = picked; thr = last; cnt = 0;
    __syncwarp();
}

__device__ __forceinline__ void knn_query(const float4 Q, int q, int lane,
                                          unsigned long long* cand) {
    unsigned long long cur = INFKEY, thr = INFKEY;
    int cnt = 0;
#pragma unroll 1
    for (int s = 0; s < Npts / 32; s++) {
        int idx = lane + 32 * s;
        float4 P = __ldg(&g_p4[idx]);
        float dot = __fmaf_rn(Q.z, P.z, __fmaf_rn(Q.y, P.y, __fmul_rn(Q.x, P.x)));
        float d = __fadd_rn(__fsub_rn(Q.w, __fmul_rn(2.0f, dot)), P.w);
        unsigned ub = __float_as_uint(d);
        ub ^= (ub >> 31) ? 0xFFFFFFFFu : 0x80000000u;
        unsigned long long k = ((unsigned long long)ub << 32) | (unsigned)idx;
        bool pred = k < thr;
        unsigned bal = __ballot_sync(0xFFFFFFFFu, pred);
        if (pred) {
            int pos = cnt + __popc(bal & ((1u << lane) - 1u));
            cand[pos] = k;
        }
        cnt += __popc(bal);
        if (cnt >= 32) knn_merge(cand, lane, cur, thr, cnt);
    }
    if (cnt > 0) knn_merge(cand, lane, cur, thr, cnt);
    if (lane < 16) g_nidx[q * KNN + lane] = (int)(unsigned)(cur & 0xFFFFFFFFull);
}

// ---------------- fused: FPS cluster (blocks 0-7, R6 core) + marker-polling kNN ----------------
__global__ void __cluster_dims__(FPS_CTAS, 1, 1) __launch_bounds__(FT, 1)
fused_kernel(float* __restrict__ out_np) {
    extern __shared__ unsigned long long dyn_smem[];
    __shared__ unsigned long long s_slots[2][FPS_SLOTS * 3];
    __shared__ unsigned long long s_mbar[2];
    const int t = threadIdx.x, warp = t >> 5, lane = t & 31;

    if (blockIdx.x < FPS_CTAS) {
        // ======================= FPS (R6 core, unmodified logic) =======================
        uint32_t cta;
        asm("mov.u32 %0, %%cluster_ctarank;" : "=r"(cta));
        const uint32_t slot_base = smem_u32(&s_slots[0][0]);
        const uint32_t mbar_base = smem_u32(&s_mbar[0]);
        if (t == 0) { mbar_init(mbar_base, 1); mbar_init(mbar_base + 8, 1); }

        float px[FPS_PPT], py[FPS_PPT], pz[FPS_PPT], pw[FPS_PPT], dist[FPS_PPT];
        unsigned gidx[FPS_PPT];
        bool valid[FPS_PPT];
#pragma unroll
        for (int j = 0; j < FPS_PPT; j++) {
            int li = t + j * FT;
            valid[j] = (li < FPS_PPC);
            int g = (int)cta * FPS_PPC + (valid[j] ? li : 0);
            float4 P = g_p4[g];
            px[j] = P.x; py[j] = P.y; pz[j] = P.z; pw[j] = P.w;
            dist[j] = 1e10f;
            gidx[j] = (unsigned)g;
        }
        const unsigned s_idx = cta * FPS_WARPS + (unsigned)warp;
        uint32_t rk[2] = {0, 0}, rm[2] = {0, 0};
        if (lane < FPS_CTAS) {
            uint32_t soff = s_idx * SLOT_BYTES;
            rk[0] = mapa_u32(slot_base + soff, (uint32_t)lane);
            rk[1] = mapa_u32(slot_base + FPS_SLOTS * SLOT_BYTES + soff, (uint32_t)lane);
            rm[0] = mapa_u32(mbar_base, (uint32_t)lane);
            rm[1] = mapa_u32(mbar_base + 8u, (uint32_t)lane);
        }

        asm volatile("barrier.cluster.arrive.aligned;" ::: "memory");
        asm volatile("barrier.cluster.wait.aligned;" ::: "memory");

        float lx, ly, lz;
        {
            float4 P0 = g_p4[0];
            lx = P0.x; ly = P0.y; lz = P0.z;
            if (cta == 0 && t == 0)
                st_global_f4(&g_q4[0], P0.x, P0.y, P0.z, P0.w);
            if (cta == 0 && t == 32) {
                out_np[0] = P0.x; out_np[1] = P0.y; out_np[2] = P0.z;
            }
        }
        unsigned ph0 = 0, ph1 = 0;

        for (int i = 1; i < Msamp; i++) {
            unsigned bd = 0, bi = 0x7FFFFFFFu;
            float bx = 0.f, by = 0.f, bz = 0.f, bw = 0.f;
#pragma unroll
            for (int j = 0; j < FPS_PPT; j++) {
                float dx = __fsub_rn(px[j], lx);
                float dy = __fsub_rn(py[j], ly);
                float dz = __fsub_rn(pz[j], lz);
                float d  = __fadd_rn(__fadd_rn(__fmul_rn(dx, dx), __fmul_rn(dy, dy)),
                                     __fmul_rn(dz, dz));
                float nd = fminf(dist[j], d);
                dist[j] = nd;
                unsigned db = __float_as_uint(nd);
                if (valid[j] && db > bd) {
                    bd = db; bi = gidx[j];
                    bx = px[j]; by = py[j]; bz = pz[j]; bw = pw[j];
                }
            }
            unsigned dmax = __reduce_max_sync(0xFFFFFFFFu, bd);
            bool cand = (bd == dmax);
            unsigned idxmin = __reduce_min_sync(0xFFFFFFFFu, cand ? bi : 0xFFFFFFFFu);
            unsigned long long key =
                ((unsigned long long)dmax << 15) | ((32767u - idxmin) & 0x7FFFu);
            const int buf = i & 1;
            unsigned src_ballot = __ballot_sync(0xFFFFFFFFu, cand && bi == idxmin);
            int src = __ffs(src_ballot) - 1;
            float wx = __shfl_sync(0xFFFFFFFFu, bx, src);
            float wy = __shfl_sync(0xFFFFFFFFu, by, src);
            float wz = __shfl_sync(0xFFFFFFFFu, bz, src);
            float ww = __shfl_sync(0xFFFFFFFFu, bw, src);
            if (lane < FPS_CTAS) {
                uint32_t rs = rk[buf], rmm = rm[buf];
                st_async_u64(rs,      key,            rmm);
                st_async_u64(rs + 8,  pack2f(wx, wy), rmm);
                st_async_u64(rs + 16, pack2f(wz, ww), rmm);
            }
            if (t == 0) mbar_expect_tx(mbar_base + 8u * (unsigned)buf,
                                       FPS_SLOTS * SLOT_BYTES);

            mbar_wait_parity(mbar_base + 8u * (unsigned)buf, buf ? ph1 : ph0);
            if (buf) ph1 ^= 1; else ph0 ^= 1;

            unsigned long long wkey;
            int sl = slot_reduce(s_slots[buf], lane, wkey);
            unsigned long long wxy = s_slots[buf][sl * 3 + 1];
            unsigned long long wzw = s_slots[buf][sl * 3 + 2];
            lx = __uint_as_float((unsigned)wxy);
            ly = __uint_as_float((unsigned)(wxy >> 32));
            lz = __uint_as_float((unsigned)wzw);
            if (cta == 0 && t == 0) {
                float w2 = __uint_as_float((unsigned)(wzw >> 32));
                st_global_f4(&g_q4[i], lx, ly, lz, w2);   // one 128-bit transaction
            }
            if (cta == 0 && t == 32) {
                out_np[3 * i] = lx; out_np[3 * i + 1] = ly; out_np[3 * i + 2] = lz;
            }
        }
        // trailing cluster barrier: no CTA exits with peers' st.async in flight
        asm volatile("barrier.cluster.arrive.aligned;" ::: "memory");
        asm volatile("barrier.cluster.wait.aligned;" ::: "memory");
        return;
    }

    // ============ kNN consumers: poll own query's marker word only ============
    const int jb = blockIdx.x - FPS_CTAS;
    unsigned long long* cand = dyn_smem + warp * 80;
    for (int q = jb * 8 + warp; q < Msamp; q += KNN_WARPS_TOT) {
        if (lane == 0) {
            const volatile unsigned* wp =
                reinterpret_cast<const volatile unsigned*>(&g_q4[q]) + 3;
            while (*wp == MARKW) __nanosleep(1024);
        }
        __syncwarp();
        float4 Q = ld_vol_f4(&g_q4[q]);
        knn_query(Q, q, lane, cand);
    }
}

// ---------------- gather + linear (GM samples/block); max/min of h + BN partials ----------------
__global__ __launch_bounds__(128) void gemm_kernel(const float* __restrict__ x,
                                                   const float* __restrict__ W) {
    __shared__ float sW[FDIM * COUT];             // 34304 B
    __shared__ float sF[GM * KNN][FDIM + 1];      // 8704 B
    const int m0 = blockIdx.x * GM, t = threadIdx.x;

    for (int i = t; i < FDIM * COUT; i += 128) sW[i] = W[i];
    for (int e = t; e < GM * KNN * FDIM; e += 128) {
        int mm = e / (KNN * FDIM);
        int rem = e - mm * (KNN * FDIM);
        int r = rem / FDIM, j = rem - r * FDIM;
        int m = m0 + mm;
        int n = g_nidx[m * KNN + r];
        float v;
        if (j < 3) {
            float4 P = g_p4[n];
            float4 Q = g_q4[m];
            v = (j == 0) ? __fsub_rn(P.x, Q.x) : (j == 1) ? __fsub_rn(P.y, Q.y)
                                                          : __fsub_rn(P.z, Q.z);
        } else {
            v = __ldg(&x[n * CIN + (j - 3)]);
        }
        sF[mm * KNN + r][j] = v;
    }
    __syncthreads();

#pragma unroll 1
    for (int mm = 0; mm < GM; mm++) {
        float acc[KNN];
#pragma unroll
        for (int r = 0; r < KNN; r++) acc[r] = 0.0f;
#pragma unroll 1
        for (int j = 0; j < FDIM; j++) {
            float wv = sW[j * COUT + t];
#pragma unroll
            for (int r = 0; r < KNN; r++)
                acc[r] = fmaf(sF[mm * KNN + r][j], wv, acc[r]);
        }
        float s1 = 0.0f, s2 = 0.0f;
        float mx = acc[0], mn = acc[0];
#pragma unroll
        for (int r = 0; r < KNN; r++) {
            s1 += acc[r];
            s2 = fmaf(acc[r], acc[r], s2);
            mx = fmaxf(mx, acc[r]);
            mn = fminf(mn, acc[r]);
        }
        const int m = m0 + mm;
        g_maxh[m * COUT + t] = mx;
        g_minh[m * COUT + t] = mn;
        g_ps [m * COUT + t] = s1;
        g_pss[m * COUT + t] = s2;
    }
}

// ---------------- deterministic BN stats reduction ----------------
__global__ __launch_bounds__(256) void stats_kernel() {
    __shared__ float s1[256], s2[256];
    const int c = blockIdx.x, t = threadIdx.x;
    float a = 0.0f, b = 0.0f;
    for (int m = t; m < Msamp; m += 256) {
        a += g_ps [m * COUT + c];
        b += g_pss[m * COUT + c];
    }
    s1[t] = a; s2[t] = b;
    __syncthreads();
    for (int o = 128; o; o >>= 1) {
        if (t < o) { s1[t] += s1[t + o]; s2[t] += s2[t + o]; }
        __syncthreads();
    }
    if (t == 0) {
        const float inv_n = 1.0f / (float)(Msamp * KNN);
        float mean = s1[0] * inv_n;
        float var  = fmaxf(s2[0] * inv_n - mean * mean, 0.0f);
        g_mean[c] = mean;
        g_rstd[c] = rsqrtf(var + BN_EPS);
    }
}

// ---------------- BN + ReLU + maxpool (exact via per-channel monotonicity) ----------------
__global__ __launch_bounds__(128) void final_kernel(const float* __restrict__ gamma,
                                                    const float* __restrict__ beta,
                                                    float* __restrict__ out_x,
                                                    float* __restrict__ out_no) {
    const int m = blockIdx.x, c = threadIdx.x;
    const float mean = g_mean[c], inv = g_rstd[c];
    const float gm = __ldg(&gamma[c]), bt = __ldg(&beta[c]);
    float h = (gm >= 0.0f) ? g_maxh[m * COUT + c] : g_minh[m * COUT + c];
    float y = fmaxf((h - mean) * inv * gm + bt, 0.0f);
    out_x[m * COUT + c] = y;
    if (out_no != nullptr && m == 0 && c == 0) *out_no = (float)Msamp;
}

// ---------------- launch ----------------
extern "C" void kernel_launch(void* const* d_in, const int* in_sizes, int n_in,
                              void* d_out, int out_size) {
    const float* p     = (const float*)d_in[0];
    const float* x     = (const float*)d_in[1];
    const float* W     = (const float*)d_in[3];
    const float* gamma = (const float*)d_in[4];
    const float* beta  = (const float*)d_in[5];
    float* out = (float*)d_out;

    const int np_elems = Msamp * 3;
    const int x_elems  = Msamp * COUT;

    float* np_dst = out;
    float* x_dst  = out + np_elems;
    float* no_dst = nullptr;
    if (out_size >= np_elems + x_elems + 1) {
        no_dst = out + np_elems + x_elems;
    } else if (out_size == x_elems) {
        float* scr; cudaGetSymbolAddress((void**)&scr, g_np_scratch);
        np_dst = scr;
        x_dst  = out;
    }

    cudaFuncSetAttribute(fused_kernel, cudaFuncAttributeMaxDynamicSharedMemorySize,
                         DYN_SMEM);

    pack_kernel  <<<(Npts + 255) / 256, 256>>>(p);
    marker_kernel<<<(Msamp + 255) / 256, 256>>>();
    fused_kernel <<<GRID_FUSED, FT, DYN_SMEM>>>(np_dst);
    gemm_kernel  <<<Msamp / GM, 128>>>(x, W);
    stats_kernel <<<COUT, 256>>>();
    final_kernel <<<Msamp, 128>>>(gamma, beta, x_dst, no_dst);
}

// round 12
// speedup vs baseline: 1.4922x; 1.0679x over previous
#include <cuda_runtime.h>
#include <cstdint>

#define Npts   20000
#define Msamp  5000
#define KNN    16
#define CIN    64
#define COUT   128
#define FDIM   (3 + CIN)          // 67
#define BN_EPS 1e-5f

// FPS cluster config: hierarchical 2-stage reduce
#define FPS_CTAS    8
#define FT          256
#define FPS_WARPS   8
#define FPS_PPC     (Npts / FPS_CTAS)         // 2500
#define FPS_PPT     10
// gemm batching (verified R11)
#define GM 2
// kNN: 2 queries per warp
#define KNN_QPW 2

// ---------------- device scratch (no allocs allowed) ----------------
__device__ float4   g_p4[Npts];
__device__ float4   g_q4[Msamp];
__device__ int      g_nidx[Msamp * KNN];
__device__ float    g_maxh[Msamp * COUT];
__device__ float    g_minh[Msamp * COUT];
__device__ float    g_ps [Msamp * COUT];
__device__ float    g_pss[Msamp * COUT];
__device__ float    g_mean[COUT];
__device__ float    g_rstd[COUT];
__device__ float    g_np_scratch[Msamp * 3];

// ---------------- PTX helpers ----------------
__device__ __forceinline__ uint32_t smem_u32(const void* p) {
    uint32_t a;
    asm("{ .reg .u64 t; cvta.to.shared.u64 t, %1; cvt.u32.u64 %0, t; }" : "=r"(a) : "l"(p));
    return a;
}
__device__ __forceinline__ uint32_t mapa_u32(uint32_t local_addr, uint32_t rank) {
    uint32_t r;
    asm("mapa.shared::cluster.u32 %0, %1, %2;" : "=r"(r) : "r"(local_addr), "r"(rank));
    return r;
}
__device__ __forceinline__ void st_async_u64(uint32_t raddr, unsigned long long v,
                                             uint32_t rmbar) {
    asm volatile("st.async.shared::cluster.mbarrier::complete_tx::bytes.b64 [%0], %1, [%2];"
                 :: "r"(raddr), "l"(v), "r"(rmbar) : "memory");
}
__device__ __forceinline__ void mbar_init(uint32_t mbar, uint32_t cnt) {
    asm volatile("mbarrier.init.shared.b64 [%0], %1;" :: "r"(mbar), "r"(cnt) : "memory");
}
__device__ __forceinline__ void mbar_expect_tx(uint32_t mbar, uint32_t bytes) {
    asm volatile("mbarrier.arrive.expect_tx.shared.b64 _, [%0], %1;"
                 :: "r"(mbar), "r"(bytes) : "memory");
}
__device__ __forceinline__ void mbar_arrive(uint32_t mbar) {
    asm volatile("mbarrier.arrive.release.cta.shared.b64 _, [%0];"
                 :: "r"(mbar) : "memory");
}
__device__ __forceinline__ void mbar_wait_parity(uint32_t mbar, uint32_t ph) {
    uint32_t done = 0;
    while (!done) {
        asm volatile(
            "{\n\t.reg .pred p;\n\t"
            "mbarrier.try_wait.parity.acquire.cluster.shared::cta.b64 p, [%1], %2, 0x989680;\n\t"
            "selp.b32 %0, 1, 0, p;\n\t}"
            : "=r"(done) : "r"(mbar), "r"(ph) : "memory");
    }
}
__device__ __forceinline__ unsigned long long pack2f(float a, float b) {
    return ((unsigned long long)__float_as_uint(b) << 32) | __float_as_uint(a);
}

// ---------------- pack ----------------
__global__ void pack_kernel(const float* __restrict__ p) {
    int i = blockIdx.x * blockDim.x + threadIdx.x;
    if (i < Npts) {
        float x = p[3 * i], y = p[3 * i + 1], z = p[3 * i + 2];
        float pp = __fadd_rn(__fadd_rn(__fmul_rn(x, x), __fmul_rn(y, y)), __fmul_rn(z, z));
        g_p4[i] = make_float4(x, y, z, pp);
    }
}

// ---------------- FPS: 8-CTA cluster, hierarchical reduce ----------------
// Stage 1: 8 warps -> local smem partials (+local mbarrier, arrive=8)
// Stage 2: warp0 reduces 8 partials, sends ONE 24B triple to every CTA
// Distance arithmetic + argmax key law identical to the verified bit-exact core.
__global__ void __cluster_dims__(FPS_CTAS, 1, 1) __launch_bounds__(FT, 1)
fps_kernel(float* __restrict__ out_np) {
    __shared__ unsigned long long s_part[2][FPS_WARPS][4];  // key, xy, zw (32B stride)
    __shared__ unsigned long long s_rslot[2][FPS_CTAS][4];  // one triple per sender CTA
    __shared__ unsigned long long s_lmbar[2];
    __shared__ unsigned long long s_rmbar[2];
    const int t = threadIdx.x, warp = t >> 5, lane = t & 31;
    uint32_t cta;
    asm("mov.u32 %0, %%cluster_ctarank;" : "=r"(cta));

    const uint32_t lmbar = smem_u32(&s_lmbar[0]);
    const uint32_t rmbar = smem_u32(&s_rmbar[0]);
    const uint32_t rslot_base = smem_u32(&s_rslot[0][0][0]);
    if (t == 0) {
        mbar_init(lmbar, FPS_WARPS); mbar_init(lmbar + 8, FPS_WARPS);
        mbar_init(rmbar, 1);         mbar_init(rmbar + 8, 1);
    }

    // register-resident slice
    float px[FPS_PPT], py[FPS_PPT], pz[FPS_PPT], pw[FPS_PPT], dist[FPS_PPT];
    unsigned gidx[FPS_PPT];
    bool valid[FPS_PPT];
#pragma unroll
    for (int j = 0; j < FPS_PPT; j++) {
        int li = t + j * FT;
        valid[j] = (li < FPS_PPC);
        int g = (int)cta * FPS_PPC + (valid[j] ? li : 0);
        float4 P = g_p4[g];
        px[j] = P.x; py[j] = P.y; pz[j] = P.z; pw[j] = P.w;
        dist[j] = 1e10f;
        gidx[j] = (unsigned)g;
    }
    // remote addresses: warp0 lane c sends to CTA c's slot[my cta]
    uint32_t rs[2] = {0, 0}, rmm[2] = {0, 0};
    if (warp == 0 && lane < FPS_CTAS) {
        uint32_t soff = (uint32_t)cta * 32u;
        rs[0]  = mapa_u32(rslot_base + soff,                   (uint32_t)lane);
        rs[1]  = mapa_u32(rslot_base + FPS_CTAS * 32u + soff,  (uint32_t)lane);
        rmm[0] = mapa_u32(rmbar,      (uint32_t)lane);
        rmm[1] = mapa_u32(rmbar + 8u, (uint32_t)lane);
    }

    asm volatile("barrier.cluster.arrive.aligned;" ::: "memory");
    asm volatile("barrier.cluster.wait.aligned;" ::: "memory");

    float lx, ly, lz;
    {
        float4 P0 = g_p4[0];
        lx = P0.x; ly = P0.y; lz = P0.z;
        if (cta == 0 && t == 0) g_q4[0] = P0;
        if (cta == 0 && t == 32) {
            out_np[0] = P0.x; out_np[1] = P0.y; out_np[2] = P0.z;
        }
    }
    unsigned lph[2] = {0, 0}, rph[2] = {0, 0};

    for (int i = 1; i < Msamp; i++) {
        const int buf = i & 1;
        // --- stage 0: update + warp argmax (verified law) ---
        unsigned bd = 0, bi = 0x7FFFFFFFu;
        float bx = 0.f, by = 0.f, bz = 0.f, bw = 0.f;
#pragma unroll
        for (int j = 0; j < FPS_PPT; j++) {
            float dx = __fsub_rn(px[j], lx);
            float dy = __fsub_rn(py[j], ly);
            float dz = __fsub_rn(pz[j], lz);
            float d  = __fadd_rn(__fadd_rn(__fmul_rn(dx, dx), __fmul_rn(dy, dy)),
                                 __fmul_rn(dz, dz));
            float nd = fminf(dist[j], d);
            dist[j] = nd;
            unsigned db = __float_as_uint(nd);
            if (valid[j] && db > bd) {
                bd = db; bi = gidx[j];
                bx = px[j]; by = py[j]; bz = pz[j]; bw = pw[j];
            }
        }
        unsigned dmax = __reduce_max_sync(0xFFFFFFFFu, bd);
        bool cnd = (bd == dmax);
        unsigned idxmin = __reduce_min_sync(0xFFFFFFFFu, cnd ? bi : 0xFFFFFFFFu);
        unsigned long long key =
            ((unsigned long long)dmax << 15) | ((32767u - idxmin) & 0x7FFFu);
        // --- stage 1: winning lane publishes warp partial to local smem ---
        if (cnd && bi == idxmin) {
            s_part[buf][warp][0] = key;
            s_part[buf][warp][1] = pack2f(bx, by);
            s_part[buf][warp][2] = pack2f(bz, bw);
        }
        __syncwarp();
        if (lane == 0) mbar_arrive(lmbar + 8u * (unsigned)buf);

        if (warp == 0) {
            // --- stage 2: reduce 8 local partials, send one triple to all CTAs ---
            mbar_wait_parity(lmbar + 8u * (unsigned)buf, lph[buf]);
            lph[buf] ^= 1;
            unsigned long long k = (lane < FPS_WARPS) ? s_part[buf][lane][0] : 0ull;
            unsigned d32 = (unsigned)(k >> 15);
            unsigned dg = __reduce_max_sync(0xFFFFFFFFu, d32);
            unsigned l15 = (d32 == dg) ? ((unsigned)k & 0x7FFFu) : 0u;
            unsigned lg = __reduce_max_sync(0xFFFFFFFFu, l15);
            unsigned long long wkey = ((unsigned long long)dg << 15) | lg;
            unsigned wb = __ballot_sync(0xFFFFFFFFu, k == wkey && lane < FPS_WARPS);
            int sl = __ffs(wb) - 1;
            unsigned long long wxy = s_part[buf][sl][1];  // broadcast LDS
            unsigned long long wzw = s_part[buf][sl][2];
            if (lane < FPS_CTAS) {
                st_async_u64(rs[buf],      wkey, rmm[buf]);
                st_async_u64(rs[buf] + 8,  wxy,  rmm[buf]);
                st_async_u64(rs[buf] + 16, wzw,  rmm[buf]);
            }
            if (lane == 0) mbar_expect_tx(rmbar + 8u * (unsigned)buf,
                                          FPS_CTAS * 24u);
        }
        // --- all warps wait for the 8 CTA triples, reduce 8 keys ---
        mbar_wait_parity(rmbar + 8u * (unsigned)buf, rph[buf]);
        rph[buf] ^= 1;
        {
            unsigned long long k = (lane < FPS_CTAS) ? s_rslot[buf][lane][0] : 0ull;
            unsigned d32 = (unsigned)(k >> 15);
            unsigned dg = __reduce_max_sync(0xFFFFFFFFu, d32);
            unsigned l15 = (d32 == dg) ? ((unsigned)k & 0x7FFFu) : 0u;
            unsigned lg = __reduce_max_sync(0xFFFFFFFFu, l15);
            unsigned long long wkey = ((unsigned long long)dg << 15) | lg;
            unsigned wb = __ballot_sync(0xFFFFFFFFu, k == wkey && lane < FPS_CTAS);
            int sl = __ffs(wb) - 1;
            unsigned long long wxy = s_rslot[buf][sl][1];  // broadcast LDS
            unsigned long long wzw = s_rslot[buf][sl][2];
            lx = __uint_as_float((unsigned)wxy);
            ly = __uint_as_float((unsigned)(wxy >> 32));
            lz = __uint_as_float((unsigned)wzw);
            if (cta == 0 && t == 0) {
                float w2 = __uint_as_float((unsigned)(wzw >> 32));
                g_q4[i] = make_float4(lx, ly, lz, w2);
            }
            if (cta == 0 && t == 32) {
                out_np[3 * i] = lx; out_np[3 * i + 1] = ly; out_np[3 * i + 2] = lz;
            }
        }
    }
    asm volatile("barrier.cluster.arrive.aligned;" ::: "memory");
    asm volatile("barrier.cluster.wait.aligned;" ::: "memory");
}

// ---------------- kNN: warp scans for 2 queries per pass (half L2 traffic) ----------------
#define INFKEY 0xFFFFFFFFFFFFFFFFull

__device__ __forceinline__ void knn_merge(unsigned long long* cand, int lane,
                                          unsigned long long& cur,
                                          unsigned long long& thr, int& cnt) {
    if (lane < 16) cand[64 + lane] = cur;
#pragma unroll
    for (int s = lane; s < 64; s += 32) if (s >= cnt) cand[s] = INFKEY;
    __syncwarp();
    unsigned long long picked = INFKEY, last = INFKEY;
#pragma unroll 1
    for (int r = 0; r < 16; r++) {
        unsigned long long a = cand[lane];
        unsigned long long b = cand[lane + 32];
        unsigned long long c = (lane < 16) ? cand[64 + lane] : INFKEY;
        unsigned long long v = a < b ? a : b;
        v = v < c ? v : c;
#pragma unroll
        for (int off = 16; off; off >>= 1) {
            unsigned long long o = __shfl_down_sync(0xFFFFFFFFu, v, off);
            if (o < v) v = o;
        }
        v = __shfl_sync(0xFFFFFFFFu, v, 0);
        if (a == v)                       cand[lane]      = INFKEY;
        else if (b == v)                  cand[lane + 32] = INFKEY;
        else if (lane < 16 && c == v)     cand[64 + lane] = INFKEY;
        __syncwarp();
        if (lane == r) picked = v;
        last = v;
    }
    cur = picked; thr = last; cnt = 0;
    __syncwarp();
}

__global__ __launch_bounds__(128) void knn_kernel() {
    __shared__ unsigned long long cand_s[4][KNN_QPW][80];
    const int warp = threadIdx.x >> 5, lane = threadIdx.x & 31;
    const int m0 = (blockIdx.x * 4 + warp) * KNN_QPW;

    float4 Q0 = g_q4[m0], Q1 = g_q4[m0 + 1];
    unsigned long long cur0 = INFKEY, thr0 = INFKEY;
    unsigned long long cur1 = INFKEY, thr1 = INFKEY;
    int cnt0 = 0, cnt1 = 0;
    unsigned long long* c0 = cand_s[warp][0];
    unsigned long long* c1 = cand_s[warp][1];

#pragma unroll 1
    for (int s = 0; s < Npts / 32; s++) {
        int idx = lane + 32 * s;
        float4 P = __ldg(&g_p4[idx]);
        // reference: qq - 2*(q@p.T) + pp, dot as XLA fma chain (verified)
        float dot0 = __fmaf_rn(Q0.z, P.z, __fmaf_rn(Q0.y, P.y, __fmul_rn(Q0.x, P.x)));
        float d0 = __fadd_rn(__fsub_rn(Q0.w, __fmul_rn(2.0f, dot0)), P.w);
        float dot1 = __fmaf_rn(Q1.z, P.z, __fmaf_rn(Q1.y, P.y, __fmul_rn(Q1.x, P.x)));
        float d1 = __fadd_rn(__fsub_rn(Q1.w, __fmul_rn(2.0f, dot1)), P.w);
        unsigned u0 = __float_as_uint(d0);
        u0 ^= (u0 >> 31) ? 0xFFFFFFFFu : 0x80000000u;
        unsigned u1 = __float_as_uint(d1);
        u1 ^= (u1 >> 31) ? 0xFFFFFFFFu : 0x80000000u;
        unsigned long long k0 = ((unsigned long long)u0 << 32) | (unsigned)idx;
        unsigned long long k1 = ((unsigned long long)u1 << 32) | (unsigned)idx;

        bool p0 = k0 < thr0;
        unsigned b0 = __ballot_sync(0xFFFFFFFFu, p0);
        if (p0) c0[cnt0 + __popc(b0 & ((1u << lane) - 1u))] = k0;
        cnt0 += __popc(b0);
        if (cnt0 >= 32) knn_merge(c0, lane, cur0, thr0, cnt0);

        bool p1 = k1 < thr1;
        unsigned b1 = __ballot_sync(0xFFFFFFFFu, p1);
        if (p1) c1[cnt1 + __popc(b1 & ((1u << lane) - 1u))] = k1;
        cnt1 += __popc(b1);
        if (cnt1 >= 32) knn_merge(c1, lane, cur1, thr1, cnt1);
    }
    if (cnt0 > 0) knn_merge(c0, lane, cur0, thr0, cnt0);
    if (cnt1 > 0) knn_merge(c1, lane, cur1, thr1, cnt1);
    if (lane < 16) {
        g_nidx[m0 * KNN + lane]       = (int)(unsigned)(cur0 & 0xFFFFFFFFull);
        g_nidx[(m0 + 1) * KNN + lane] = (int)(unsigned)(cur1 & 0xFFFFFFFFull);
    }
}

// ---------------- gather + linear (GM samples/block); max/min of h + BN partials ----------------
__global__ __launch_bounds__(128) void gemm_kernel(const float* __restrict__ x,
                                                   const float* __restrict__ W) {
    __shared__ float sW[FDIM * COUT];
    __shared__ float sF[GM * KNN][FDIM + 1];
    const int m0 = blockIdx.x * GM, t = threadIdx.x;

    for (int i = t; i < FDIM * COUT; i += 128) sW[i] = W[i];
    for (int e = t; e < GM * KNN * FDIM; e += 128) {
        int mm = e / (KNN * FDIM);
        int rem = e - mm * (KNN * FDIM);
        int r = rem / FDIM, j = rem - r * FDIM;
        int m = m0 + mm;
        int n = g_nidx[m * KNN + r];
        float v;
        if (j < 3) {
            float4 P = g_p4[n];
            float4 Q = g_q4[m];
            v = (j == 0) ? __fsub_rn(P.x, Q.x) : (j == 1) ? __fsub_rn(P.y, Q.y)
                                                          : __fsub_rn(P.z, Q.z);
        } else {
            v = __ldg(&x[n * CIN + (j - 3)]);
        }
        sF[mm * KNN + r][j] = v;
    }
    __syncthreads();

#pragma unroll 1
    for (int mm = 0; mm < GM; mm++) {
        float acc[KNN];
#pragma unroll
        for (int r = 0; r < KNN; r++) acc[r] = 0.0f;
#pragma unroll 1
        for (int j = 0; j < FDIM; j++) {
            float wv = sW[j * COUT + t];
#pragma unroll
            for (int r = 0; r < KNN; r++)
                acc[r] = fmaf(sF[mm * KNN + r][j], wv, acc[r]);
        }
        float s1 = 0.0f, s2 = 0.0f;
        float mx = acc[0], mn = acc[0];
#pragma unroll
        for (int r = 0; r < KNN; r++) {
            s1 += acc[r];
            s2 = fmaf(acc[r], acc[r], s2);
            mx = fmaxf(mx, acc[r]);
            mn = fminf(mn, acc[r]);
        }
        const int m = m0 + mm;
        g_maxh[m * COUT + t] = mx;
        g_minh[m * COUT + t] = mn;
        g_ps [m * COUT + t] = s1;
        g_pss[m * COUT + t] = s2;
    }
}

// ---------------- deterministic BN stats reduction ----------------
__global__ __launch_bounds__(256) void stats_kernel() {
    __shared__ float s1[256], s2[256];
    const int c = blockIdx.x, t = threadIdx.x;
    float a = 0.0f, b = 0.0f;
    for (int m = t; m < Msamp; m += 256) {
        a += g_ps [m * COUT + c];
        b += g_pss[m * COUT + c];
    }
    s1[t] = a; s2[t] = b;
    __syncthreads();
    for (int o = 128; o; o >>= 1) {
        if (t < o) { s1[t] += s1[t + o]; s2[t] += s2[t + o]; }
        __syncthreads();
    }
    if (t == 0) {
        const float inv_n = 1.0f / (float)(Msamp * KNN);
        float mean = s1[0] * inv_n;
        float var  = fmaxf(s2[0] * inv_n - mean * mean, 0.0f);
        g_mean[c] = mean;
        g_rstd[c] = rsqrtf(var + BN_EPS);
    }
}

// ---------------- BN + ReLU + maxpool (exact via per-channel monotonicity) ----------------
__global__ __launch_bounds__(128) void final_kernel(const float* __restrict__ gamma,
                                                    const float* __restrict__ beta,
                                                    float* __restrict__ out_x,
                                                    float* __restrict__ out_no) {
    const int m = blockIdx.x, c = threadIdx.x;
    const float mean = g_mean[c], inv = g_rstd[c];
    const float gm = __ldg(&gamma[c]), bt = __ldg(&beta[c]);
    float h = (gm >= 0.0f) ? g_maxh[m * COUT + c] : g_minh[m * COUT + c];
    float y = fmaxf((h - mean) * inv * gm + bt, 0.0f);
    out_x[m * COUT + c] = y;
    if (out_no != nullptr && m == 0 && c == 0) *out_no = (float)Msamp;
}

// ---------------- launch ----------------
extern "C" void kernel_launch(void* const* d_in, const int* in_sizes, int n_in,
                              void* d_out, int out_size) {
    const float* p     = (const float*)d_in[0];
    const float* x     = (const float*)d_in[1];
    const float* W     = (const float*)d_in[3];
    const float* gamma = (const float*)d_in[4];
    const float* beta  = (const float*)d_in[5];
    float* out = (float*)d_out;

    const int np_elems = Msamp * 3;
    const int x_elems  = Msamp * COUT;

    float* np_dst = out;
    float* x_dst  = out + np_elems;
    float* no_dst = nullptr;
    if (out_size >= np_elems + x_elems + 1) {
        no_dst = out + np_elems + x_elems;
    } else if (out_size == x_elems) {
        float* scr; cudaGetSymbolAddress((void**)&scr, g_np_scratch);
        np_dst = scr;
        x_dst  = out;
    }

    pack_kernel <<<(Npts + 255) / 256, 256>>>(p);
    fps_kernel  <<<FPS_CTAS, FT>>>(np_dst);
    knn_kernel  <<<Msamp / (4 * KNN_QPW), 128>>>();
    gemm_kernel <<<Msamp / GM, 128>>>(x, W);
    stats_kernel<<<COUT, 256>>>();
    final_kernel<<<Msamp, 128>>>(gamma, beta, x_dst, no_dst);
}